// round 5
// baseline (speedup 1.0000x reference)
#include <cuda_runtime.h>

// out[b,o] = tanh( sum_{j<3} tanh(x[b]·w_in[:,j] - thr_h[j]) * w_ho[j,o] + C_o - 0.5 )
// C_o = sum_{j=3..63} tanh(-thr_h[j]) * w_ho[j,o]
//
// HBM-bound: stream x (128 MB) once. w_in register-cached (48 regs/thread).
// Rows are software-pipelined: next row's 4 LDG.128/thread are issued before
// consuming the current row's registers, so loads stay in flight through the
// FMA/reduce/barrier tail (fixes the 43.7%-DRAM duty-cycle limit of R3).

#define NTHREADS 256
#define NBLOCKS  296          // 148 SMs * 2 resident blocks (~100 regs/thread)
#define BATCH_N  8192
#define DIM_N    4096
#define OUT_N    8

__global__ void __launch_bounds__(NTHREADS, 2)
enn_kernel(const float* __restrict__ x,
           const float* __restrict__ w_in,
           const float* __restrict__ w_ho,
           const float* __restrict__ thr_h,
           float* __restrict__ out)
{
    __shared__ float s_part[2][3][8]; // [parity][hidden j][warp]
    __shared__ float s_c[OUT_N];      // C_o - 0.5
    __shared__ float s_who[3][OUT_N];
    __shared__ float s_thr[3];

    const int t    = threadIdx.x;
    const int lane = t & 31;
    const int warp = t >> 5;

    // ---- one-time per-block prologue ----
    if (t < 24) s_who[t / 8][t % 8] = w_ho[t];          // w_ho rows 0..2
    if (t < 3)  s_thr[t] = thr_h[t];
    if (t < OUT_N) {
        float c = -0.5f;
        #pragma unroll 1
        for (int j = 3; j < 64; j++)
            c = fmaf(tanhf(-thr_h[j]), w_ho[j * OUT_N + t], c);
        s_c[t] = c;
    }

    // ---- register-cache w_in: thread t owns float4-chunks {t, t+256, t+512, t+768}
    // chunk f covers dims 4f..4f+3 -> 12 consecutive w_in floats at index 12f
    // (byte offset 48f: always 16B-aligned).
    float4 w[4][3];
    #pragma unroll
    for (int k = 0; k < 4; k++) {
        const int f = t + k * NTHREADS;
        const float4* wp = reinterpret_cast<const float4*>(w_in + 12 * f);
        w[k][0] = wp[0];
        w[k][1] = wp[1];
        w[k][2] = wp[2];
    }
    __syncthreads();

    // ---- software-pipelined persistent row loop ----
    float4 xv[2][4];
    int row = blockIdx.x;
    if (row < BATCH_N) {
        {   // prologue: load first row into buffer 0
            const float4* xr = reinterpret_cast<const float4*>(x + (size_t)row * DIM_N);
            #pragma unroll
            for (int k = 0; k < 4; k++) xv[0][k] = xr[t + k * NTHREADS];
        }

        int parity = 0;
        for (; row < BATCH_N; row += gridDim.x, parity ^= 1) {
            const int nrow = row + gridDim.x;
            const int pb = parity & 1, nb = pb ^ 1;

            // issue next row's loads NOW — they stay in flight through the
            // entire compute/reduce/barrier tail below.
            if (nrow < BATCH_N) {
                const float4* xr = reinterpret_cast<const float4*>(x + (size_t)nrow * DIM_N);
                #pragma unroll
                for (int k = 0; k < 4; k++) xv[nb][k] = xr[t + k * NTHREADS];
            }

            float a0 = 0.f, a1 = 0.f, a2 = 0.f;
            #pragma unroll
            for (int k = 0; k < 4; k++) {
                const float4 v = xv[pb][k];
                // layout: W0=(d0j0,d0j1,d0j2,d1j0) W1=(d1j1,d1j2,d2j0,d2j1) W2=(d2j2,d3j0,d3j1,d3j2)
                a0 = fmaf(v.x, w[k][0].x, a0);
                a0 = fmaf(v.y, w[k][0].w, a0);
                a0 = fmaf(v.z, w[k][1].z, a0);
                a0 = fmaf(v.w, w[k][2].y, a0);

                a1 = fmaf(v.x, w[k][0].y, a1);
                a1 = fmaf(v.y, w[k][1].x, a1);
                a1 = fmaf(v.z, w[k][1].w, a1);
                a1 = fmaf(v.w, w[k][2].z, a1);

                a2 = fmaf(v.x, w[k][0].z, a2);
                a2 = fmaf(v.y, w[k][1].y, a2);
                a2 = fmaf(v.z, w[k][2].x, a2);
                a2 = fmaf(v.w, w[k][2].w, a2);
            }

            // warp tree-reduce the 3 partial dots
            #pragma unroll
            for (int off = 16; off > 0; off >>= 1) {
                a0 += __shfl_xor_sync(0xFFFFFFFFu, a0, off);
                a1 += __shfl_xor_sync(0xFFFFFFFFu, a1, off);
                a2 += __shfl_xor_sync(0xFFFFFFFFu, a2, off);
            }
            if (lane == 0) {
                s_part[pb][0][warp] = a0;
                s_part[pb][1][warp] = a1;
                s_part[pb][2][warp] = a2;
            }
            __syncthreads();   // orders this row's smem writes before reads;
                               // next row uses the other parity buffer (no WAR).

            if (t < OUT_N) {
                float s0 = 0.f, s1 = 0.f, s2 = 0.f;
                #pragma unroll
                for (int wv = 0; wv < 8; wv++) {
                    s0 += s_part[pb][0][wv];
                    s1 += s_part[pb][1][wv];
                    s2 += s_part[pb][2][wv];
                }
                const float t0 = tanhf(s0 - s_thr[0]);
                const float t1 = tanhf(s1 - s_thr[1]);
                const float t2 = tanhf(s2 - s_thr[2]);
                float vv = s_c[t];
                vv = fmaf(t0, s_who[0][t], vv);
                vv = fmaf(t1, s_who[1][t], vv);
                vv = fmaf(t2, s_who[2][t], vv);
                out[row * OUT_N + t] = tanhf(vv);
            }
        }
    }
}

extern "C" void kernel_launch(void* const* d_in, const int* in_sizes, int n_in,
                              void* d_out, int out_size)
{
    const float* x     = (const float*)d_in[0];   // [8192, 4096]
    const float* w_in  = (const float*)d_in[1];   // [4096, 3]
    const float* w_ho  = (const float*)d_in[2];   // [64, 8]
    const float* thr_h = (const float*)d_in[3];   // [64]
    float* out = (float*)d_out;                   // [8192, 8]

    enn_kernel<<<NBLOCKS, NTHREADS>>>(x, w_in, w_ho, thr_h, out);
}

// round 6
// speedup vs baseline: 1.5094x; 1.5094x over previous
#include <cuda_runtime.h>
#include <cstdint>

// out[b,o] = tanh( sum_{j<3} tanh(x[b]·w_in[:,j] - thr_h[j]) * w_ho[j,o] + C_o - 0.5 )
// C_o = sum_{j=3..63} tanh(-thr_h[j]) * w_ho[j,o]
//
// HBM-bound: stream x (128 MB) once. w_in register-cached (48 regs/thread).
// x rows are staged gmem->smem with cp.async (double-buffered): the async copy
// of row r+1 streams through the LSU while row r's compute/reduce/barrier tail
// runs. Hardware-async copies cannot be reordered/sunk by ptxas (the failure
// mode of the R5 register prefetch).

#define NTHREADS 256
#define NBLOCKS  444          // 148 SMs * 3 resident blocks
#define BATCH_N  8192
#define DIM_N    4096
#define OUT_N    8

__device__ __forceinline__ void cp_async16(uint32_t dst_smem, const void* src) {
    asm volatile("cp.async.cg.shared.global [%0], [%1], 16;" :: "r"(dst_smem), "l"(src));
}
__device__ __forceinline__ void cp_commit() {
    asm volatile("cp.async.commit_group;");
}
__device__ __forceinline__ void cp_wait1() {
    asm volatile("cp.async.wait_group 1;");
}

__global__ void __launch_bounds__(NTHREADS, 3)
enn_kernel(const float* __restrict__ x,
           const float* __restrict__ w_in,
           const float* __restrict__ w_ho,
           const float* __restrict__ thr_h,
           float* __restrict__ out)
{
    __shared__ float4 s_x[2][DIM_N / 4];   // 2 x 16 KB row tiles
    __shared__ float  s_part[2][3][8];     // [parity][hidden j][warp]
    __shared__ float  s_c[OUT_N];          // C_o - 0.5
    __shared__ float  s_who[3][OUT_N];
    __shared__ float  s_thr[3];

    const int t    = threadIdx.x;
    const int lane = t & 31;
    const int warp = t >> 5;

    // ---- one-time per-block prologue ----
    if (t < 24) s_who[t / 8][t % 8] = w_ho[t];          // w_ho rows 0..2
    if (t < 3)  s_thr[t] = thr_h[t];
    if (t < OUT_N) {
        float c = -0.5f;
        #pragma unroll 1
        for (int j = 3; j < 64; j++)
            c = fmaf(tanhf(-thr_h[j]), w_ho[j * OUT_N + t], c);
        s_c[t] = c;
    }

    // ---- register-cache w_in: thread t owns float4-chunks {t, t+256, t+512, t+768}
    // chunk f covers dims 4f..4f+3 -> 12 consecutive w_in floats at index 12f
    // (byte offset 48f: always 16B-aligned).
    float4 w[4][3];
    #pragma unroll
    for (int k = 0; k < 4; k++) {
        const int f = t + k * NTHREADS;
        const float4* wp = reinterpret_cast<const float4*>(w_in + 12 * f);
        w[k][0] = wp[0];
        w[k][1] = wp[1];
        w[k][2] = wp[2];
    }

    const uint32_t s_x_base = (uint32_t)__cvta_generic_to_shared(&s_x[0][0]);

    // ---- prologue: async-copy first row into buffer 0 ----
    int row = blockIdx.x;          // always < BATCH_N (grid 444 < 8192)
    {
        const char* src = (const char*)(x + (size_t)row * DIM_N);
        #pragma unroll
        for (int k = 0; k < 4; k++)
            cp_async16(s_x_base + (uint32_t)(t * 16 + k * 4096),
                       src + t * 16 + k * 4096);
        cp_commit();
    }
    __syncthreads();   // covers the s_c / s_who / s_thr init too

    int parity = 0;
    for (; row < BATCH_N; row += gridDim.x, parity ^= 1) {
        const int nrow = row + gridDim.x;
        const int pb = parity & 1, nb = pb ^ 1;

        // issue next row's async copy into the other buffer; it streams
        // through the LSU while this row's compute/reduce/barriers run.
        if (nrow < BATCH_N) {
            const char* src = (const char*)(x + (size_t)nrow * DIM_N);
            #pragma unroll
            for (int k = 0; k < 4; k++)
                cp_async16(s_x_base + (uint32_t)(nb * 16384 + t * 16 + k * 4096),
                           src + t * 16 + k * 4096);
        }
        cp_commit();   // always commit (possibly empty) so wait_group 1 below
                       // always leaves exactly the newest group pending.
        cp_wait1();    // current row's tile (older group) is complete
        __syncthreads();   // make all threads' copied data visible

        float a0 = 0.f, a1 = 0.f, a2 = 0.f;
        #pragma unroll
        for (int k = 0; k < 4; k++) {
            const float4 v = s_x[pb][t + k * NTHREADS];   // conflict-free LDS.128
            // layout: W0=(d0j0,d0j1,d0j2,d1j0) W1=(d1j1,d1j2,d2j0,d2j1) W2=(d2j2,d3j0,d3j1,d3j2)
            a0 = fmaf(v.x, w[k][0].x, a0);
            a0 = fmaf(v.y, w[k][0].w, a0);
            a0 = fmaf(v.z, w[k][1].z, a0);
            a0 = fmaf(v.w, w[k][2].y, a0);

            a1 = fmaf(v.x, w[k][0].y, a1);
            a1 = fmaf(v.y, w[k][1].x, a1);
            a1 = fmaf(v.z, w[k][1].w, a1);
            a1 = fmaf(v.w, w[k][2].z, a1);

            a2 = fmaf(v.x, w[k][0].z, a2);
            a2 = fmaf(v.y, w[k][1].y, a2);
            a2 = fmaf(v.z, w[k][2].x, a2);
            a2 = fmaf(v.w, w[k][2].w, a2);
        }

        // warp tree-reduce the 3 partial dots
        #pragma unroll
        for (int off = 16; off > 0; off >>= 1) {
            a0 += __shfl_xor_sync(0xFFFFFFFFu, a0, off);
            a1 += __shfl_xor_sync(0xFFFFFFFFu, a1, off);
            a2 += __shfl_xor_sync(0xFFFFFFFFu, a2, off);
        }
        if (lane == 0) {
            s_part[pb][0][warp] = a0;
            s_part[pb][1][warp] = a1;
            s_part[pb][2][warp] = a2;
        }
        __syncthreads();   // (a) s_part writes -> reads below
                           // (b) all reads of s_x[pb] done before the NEXT
                           //     iteration issues async writes into s_x[pb]

        if (t < OUT_N) {
            float s0 = 0.f, s1 = 0.f, s2 = 0.f;
            #pragma unroll
            for (int wv = 0; wv < 8; wv++) {
                s0 += s_part[pb][0][wv];
                s1 += s_part[pb][1][wv];
                s2 += s_part[pb][2][wv];
            }
            const float t0 = tanhf(s0 - s_thr[0]);
            const float t1 = tanhf(s1 - s_thr[1]);
            const float t2 = tanhf(s2 - s_thr[2]);
            float vv = s_c[t];
            vv = fmaf(t0, s_who[0][t], vv);
            vv = fmaf(t1, s_who[1][t], vv);
            vv = fmaf(t2, s_who[2][t], vv);
            out[row * OUT_N + t] = tanhf(vv);
        }
    }
}

extern "C" void kernel_launch(void* const* d_in, const int* in_sizes, int n_in,
                              void* d_out, int out_size)
{
    const float* x     = (const float*)d_in[0];   // [8192, 4096]
    const float* w_in  = (const float*)d_in[1];   // [4096, 3]
    const float* w_ho  = (const float*)d_in[2];   // [64, 8]
    const float* thr_h = (const float*)d_in[3];   // [64]
    float* out = (float*)d_out;                   // [8192, 8]

    enn_kernel<<<NBLOCKS, NTHREADS>>>(x, w_in, w_ho, thr_h, out);
}